// round 7
// baseline (speedup 1.0000x reference)
#include <cuda_runtime.h>
#include <cuda_bf16.h>
#include <stdint.h>

// LSTM_3444563771996 : I=28, H=64, T=128, B=4096, OUT=10
// Persistent per-CTA LSTM, bf16 hi/lo split mma.sync.
// 1024 threads = 4 independent groups of 256, each owning 8 batch rows with
// private named barriers -> 4 in-flight GEMM/ACT chains hide pipe latency.

#define TI   128
#define II   28
#define HH   64
#define GG   256
#define KK   92
#define BB   4096
#define OUTD 10
#define MB   32      // batch rows per CTA (8 per group)
#define NTHR 1024
#define KST  104     // bf16 row stride (208 B)
#define GST  33      // Gs float stride

#define SM_WHI 0
#define SM_WLO (SM_WHI + GG * KST * 2)     //  53248
#define SM_AHI (SM_WLO + GG * KST * 2)     // 106496
#define SM_ALO (SM_AHI + MB * KST * 2)     // 113152
#define SM_GS  (SM_ALO + MB * KST * 2)     // 119808
#define SM_HS  (SM_GS  + GG * GST * 4)     // 153600
#define SMEM_BYTES (SM_HS + MB * HH * 4)   // 161792

typedef unsigned long long u64;

#define LDSM4(r, addr)                                                        \
    asm volatile("ldmatrix.sync.aligned.m8n8.x4.shared.b16 {%0,%1,%2,%3}, [%4];" \
                 : "=r"((r)[0]), "=r"((r)[1]), "=r"((r)[2]), "=r"((r)[3])     \
                 : "r"(addr))

#define LDSM2(r, addr)                                                        \
    asm volatile("ldmatrix.sync.aligned.m8n8.x2.shared.b16 {%0,%1}, [%2];"    \
                 : "=r"((r)[0]), "=r"((r)[1])                                 \
                 : "r"(addr))

#define MMA16816(d, a, b0_, b1_)                                              \
    asm volatile("mma.sync.aligned.m16n8k16.row.col.f32.bf16.bf16.f32 "       \
                 "{%0,%1,%2,%3}, {%4,%5,%6,%7}, {%8,%9}, {%0,%1,%2,%3};"      \
                 : "+f"((d)[0]), "+f"((d)[1]), "+f"((d)[2]), "+f"((d)[3])     \
                 : "r"((a)[0]), "r"((a)[1]), "r"((a)[2]), "r"((a)[3]),        \
                   "r"(b0_), "r"(b1_))

#define GBAR(id)                                                              \
    asm volatile("bar.sync %0, %1;" :: "r"(id), "r"(256) : "memory")

static __device__ __forceinline__ uint32_t smem_u32(const void* p) {
    uint32_t a;
    asm("{ .reg .u64 t; cvta.to.shared.u64 t, %1; cvt.u32.u64 %0, t; }" : "=r"(a) : "l"(p));
    return a;
}
static __device__ __forceinline__ void split_bf16(float v, uint16_t& hi, uint16_t& lo) {
    __nv_bfloat16 h = __float2bfloat16_rn(v);
    __nv_bfloat16 l = __float2bfloat16_rn(v - __bfloat162float(h));
    hi = __bfloat16_as_ushort(h);
    lo = __bfloat16_as_ushort(l);
}
static __device__ __forceinline__ float sigm_(float v) {
    return __fdividef(1.0f, 1.0f + __expf(-v));
}
static __device__ __forceinline__ float tanh_(float v) {
    float e = __expf(-2.0f * v);
    return __fdividef(2.0f, 1.0f + e) - 1.0f;
}

__global__ __launch_bounds__(NTHR, 1)
void lstm_kernel(const float* __restrict__ x,
                 const float* __restrict__ W_ih, const float* __restrict__ W_hh,
                 const float* __restrict__ b_ih, const float* __restrict__ b_hh,
                 const float* __restrict__ W_out, const float* __restrict__ b_out,
                 float* __restrict__ out)
{
    extern __shared__ char smem[];
    const uint32_t sb = smem_u32(smem);
    float* Gs = (float*)(smem + SM_GS);
    float* Hs = (float*)(smem + SM_HS);

    const int tid   = threadIdx.x;
    const int lane  = tid & 31;
    const int group = tid >> 8;          // 0..3: owns batch rows [group*8, +8)
    const int gtid  = tid & 255;
    const int gwarp = (tid >> 5) & 7;    // warp within group -> 32-gate slice
    const int b0    = blockIdx.x * MB;
    const int barid = 1 + group;

    // ---- zero W / A staging (K padding + h0 = 0) ----
    for (int i = tid; i < (SM_GS - SM_WHI) / 4; i += NTHR)
        ((uint32_t*)smem)[i] = 0u;
    __syncthreads();

    // ---- stage W hi/lo: [gate][k] bf16 ----
    for (int idx = tid; idx < GG * KK; idx += NTHR) {
        int g = idx / KK, k = idx - g * KK;
        float v = (k < II) ? W_ih[g * II + k] : W_hh[g * HH + (k - II)];
        uint16_t hi, lo; split_bf16(v, hi, lo);
        *(uint16_t*)(smem + SM_WHI + (g * KST + k) * 2) = hi;
        *(uint16_t*)(smem + SM_WLO + (g * KST + k) * 2) = lo;
    }

    // ---- ldmatrix lane offsets ----
    const int l7 = lane & 7, lg = lane >> 3;
    const int wrow = l7 + ((lg & 1) << 3);   // W x4 tiles {r0-7@k0, r8-15@k0, r0-7@k8, r8-15@k8}
    const int wkh  = lg >> 1;
    // B x2 tiles {n0-7@k0, n0-7@k8}; lanes 0..15 supply addresses
    const int arow = group * 8 + l7;
    const int akh  = (lane >> 3) & 1;

    const uint32_t woffH = sb + SM_WHI + (((gwarp * 32 + wrow) * KST) + wkh * 8) * 2;
    const uint32_t woffL = sb + SM_WLO + (((gwarp * 32 + wrow) * KST) + wkh * 8) * 2;
    const uint32_t aoffH = sb + SM_AHI + ((arow * KST) + akh * 8) * 2;
    const uint32_t aoffL = sb + SM_ALO + ((arow * KST) + akh * 8) * 2;

    // ---- accumulator-row biases (folded into acc init) ----
    const int grow = lane >> 2;          // accum row within m8
    const int bcol = (lane & 3) * 2;     // accum col pair
    float biasA[2], biasB[2];
#pragma unroll
    for (int mt = 0; mt < 2; ++mt) {
        int g1 = gwarp * 32 + mt * 16 + grow;
        biasA[mt] = b_ih[g1]     + b_hh[g1];
        biasB[mt] = b_ih[g1 + 8] + b_hh[g1 + 8];
    }

    // ---- activation-phase constants (256 threads/group, 2 rows each) ----
    const int u  = gtid & 63;
    const int rg = gtid >> 6;            // 0..3
    const int r0 = group * 8 + rg * 2;   // global batch row base
    float c[2];
    c[0] = 0.0f; c[1] = 0.0f;

    __syncthreads();

    for (int t = 0; t < TI; ++t) {
        // ---- stage x_t for this group's 8 rows (56 threads) ----
        if (gtid < 8 * 7) {
            int row = group * 8 + gtid / 7, seg = gtid % 7;
            const float4 xv = *reinterpret_cast<const float4*>(
                x + ((size_t)(b0 + row) * TI + t) * II + seg * 4);
            uint16_t h0,l0,h1,l1,h2,l2,h3,l3;
            split_bf16(xv.x, h0, l0); split_bf16(xv.y, h1, l1);
            split_bf16(xv.z, h2, l2); split_bf16(xv.w, h3, l3);
            u64 ph = (u64)h0 | ((u64)h1 << 16) | ((u64)h2 << 32) | ((u64)h3 << 48);
            u64 pl = (u64)l0 | ((u64)l1 << 16) | ((u64)l2 << 32) | ((u64)l3 << 48);
            *(u64*)(smem + SM_AHI + (row * KST + seg * 4) * 2) = ph;
            *(u64*)(smem + SM_ALO + (row * KST + seg * 4) * 2) = pl;
        }
        GBAR(barid);   // group's x_t + h(t-1) visible

        // ---- GEMM: 36 HMMA/warp, D[256 gates, 8 batch] ----
        float acc[2][4];
#pragma unroll
        for (int mt = 0; mt < 2; ++mt) {
            acc[mt][0] = biasA[mt]; acc[mt][1] = biasA[mt];
            acc[mt][2] = biasB[mt]; acc[mt][3] = biasB[mt];
        }

#pragma unroll
        for (int kc = 0; kc < 6; ++kc) {
            const uint32_t ko = kc * 32;
            uint32_t whi0[4], whi1[4], wlo0[4], wlo1[4], bhi[2], blo[2];
            LDSM4(whi0, woffH + ko);
            LDSM4(whi1, woffH + 16 * KST * 2 + ko);
            LDSM4(wlo0, woffL + ko);
            LDSM4(wlo1, woffL + 16 * KST * 2 + ko);
            LDSM2(bhi, aoffH + ko);
            LDSM2(blo, aoffL + ko);
            MMA16816(acc[0], whi0, bhi[0], bhi[1]);
            MMA16816(acc[0], whi0, blo[0], blo[1]);
            MMA16816(acc[0], wlo0, bhi[0], bhi[1]);
            MMA16816(acc[1], whi1, bhi[0], bhi[1]);
            MMA16816(acc[1], whi1, blo[0], blo[1]);
            MMA16816(acc[1], wlo1, bhi[0], bhi[1]);
        }

        // ---- store gates to Gs[gate][group cols] ----
#pragma unroll
        for (int mt = 0; mt < 2; ++mt) {
            const int g1 = gwarp * 32 + mt * 16 + grow;
            const int bb = group * 8 + bcol;
            Gs[g1 * GST + bb]           = acc[mt][0];
            Gs[g1 * GST + bb + 1]       = acc[mt][1];
            Gs[(g1 + 8) * GST + bb]     = acc[mt][2];
            Gs[(g1 + 8) * GST + bb + 1] = acc[mt][3];
        }
        GBAR(barid);   // gates visible; group's A reads complete

        // ---- activations + state update; h -> A[row][28+u] hi/lo ----
#pragma unroll
        for (int r = 0; r < 2; ++r) {
            const int row = r0 + r;
            float ig = sigm_(Gs[u * GST + row]);
            float fg = sigm_(Gs[(u + 64) * GST + row]);
            float gg = tanh_(Gs[(u + 128) * GST + row]);
            float og = sigm_(Gs[(u + 192) * GST + row]);
            float cv = fmaf(fg, c[r], ig * gg);
            c[r] = cv;
            float hv = og * tanh_(cv);
            uint16_t hh, hl; split_bf16(hv, hh, hl);
            *(uint16_t*)(smem + SM_AHI + (row * KST + II + u) * 2) = hh;
            *(uint16_t*)(smem + SM_ALO + (row * KST + II + u) * 2) = hl;
            if (t == TI - 1) Hs[row * HH + u] = hv;
        }
        // next iteration's group barrier orders h writes before ldmatrix reads.
    }

    // ---- final linear: out = h_T @ W_out^T + b_out ----
    __syncthreads();
    for (int idx = tid; idx < OUTD * HH; idx += NTHR) Gs[idx] = W_out[idx];
    if (tid < OUTD) Gs[OUTD * HH + tid] = b_out[tid];
    __syncthreads();

    for (int cell = tid; cell < MB * OUTD; cell += NTHR) {
        int row = cell / OUTD;
        int o   = cell - row * OUTD;
        float s = Gs[OUTD * HH + o];
#pragma unroll
        for (int j = 0; j < HH; ++j)
            s = fmaf(Hs[row * HH + j], Gs[o * HH + j], s);
        out[(size_t)(b0 + row) * OUTD + o] = s;
    }
}

extern "C" void kernel_launch(void* const* d_in, const int* in_sizes, int n_in,
                              void* d_out, int out_size)
{
    const float* x     = (const float*)d_in[0];
    const float* W_ih  = (const float*)d_in[1];
    const float* W_hh  = (const float*)d_in[2];
    const float* b_ih  = (const float*)d_in[3];
    const float* b_hh  = (const float*)d_in[4];
    const float* W_out = (const float*)d_in[5];
    const float* b_out = (const float*)d_in[6];
    float* outp = (float*)d_out;

    cudaFuncSetAttribute(lstm_kernel,
                         cudaFuncAttributeMaxDynamicSharedMemorySize, SMEM_BYTES);
    lstm_kernel<<<BB / MB, NTHR, SMEM_BYTES>>>(x, W_ih, W_hh, b_ih, b_hh,
                                               W_out, b_out, outp);
}

// round 8
// speedup vs baseline: 1.3530x; 1.3530x over previous
#include <cuda_runtime.h>
#include <cuda_bf16.h>
#include <stdint.h>

// LSTM_3444563771996 : I=28, H=64, T=128, B=4096, OUT=10
// Warp-specialized persistent LSTM: 8 GEMM warps (tensor) + 8 ACT warps
// (MUFU/LDS), 2 batch half-groups pipelined via named barriers.
// Gates GEMM: bf16 hi/lo split mma.sync, fp32 accum:
//   D += Whi*Ahi + Whi*Alo + Wlo*Ahi

#define TI   128
#define II   28
#define HH   64
#define GG   256
#define KK   92
#define BB   4096
#define OUTD 10
#define MB   32      // batch rows per CTA (16 per group)
#define NTHR 512
#define KST  104     // bf16 row stride (208 B)
#define GST  33      // Gs float stride

#define SM_WHI 0
#define SM_WLO (SM_WHI + GG * KST * 2)     //  53248
#define SM_AHI (SM_WLO + GG * KST * 2)     // 106496
#define SM_ALO (SM_AHI + MB * KST * 2)     // 113152
#define SM_GS  (SM_ALO + MB * KST * 2)     // 119808
#define SM_HS  (SM_GS  + GG * GST * 4)     // 153600
#define SMEM_BYTES (SM_HS + MB * HH * 4)   // 161792

typedef unsigned long long u64;

#define LDSM4(r, addr)                                                        \
    asm volatile("ldmatrix.sync.aligned.m8n8.x4.shared.b16 {%0,%1,%2,%3}, [%4];" \
                 : "=r"((r)[0]), "=r"((r)[1]), "=r"((r)[2]), "=r"((r)[3])     \
                 : "r"(addr))

#define MMA16816(d, a, b0_, b1_)                                              \
    asm volatile("mma.sync.aligned.m16n8k16.row.col.f32.bf16.bf16.f32 "       \
                 "{%0,%1,%2,%3}, {%4,%5,%6,%7}, {%8,%9}, {%0,%1,%2,%3};"      \
                 : "+f"((d)[0]), "+f"((d)[1]), "+f"((d)[2]), "+f"((d)[3])     \
                 : "r"((a)[0]), "r"((a)[1]), "r"((a)[2]), "r"((a)[3]),        \
                   "r"(b0_), "r"(b1_))

// producer/consumer named barriers: 256 producers arrive, 256 consumers sync.
#define BSYNC(id) asm volatile("bar.sync %0, %1;"   :: "r"(id), "r"(NTHR) : "memory")
#define BARR(id)  asm volatile("bar.arrive %0, %1;" :: "r"(id), "r"(NTHR) : "memory")

static __device__ __forceinline__ uint32_t smem_u32(const void* p) {
    uint32_t a;
    asm("{ .reg .u64 t; cvta.to.shared.u64 t, %1; cvt.u32.u64 %0, t; }" : "=r"(a) : "l"(p));
    return a;
}
static __device__ __forceinline__ void split_bf16(float v, uint16_t& hi, uint16_t& lo) {
    __nv_bfloat16 h = __float2bfloat16_rn(v);
    __nv_bfloat16 l = __float2bfloat16_rn(v - __bfloat162float(h));
    hi = __bfloat16_as_ushort(h);
    lo = __bfloat16_as_ushort(l);
}
static __device__ __forceinline__ float sigm_(float v) {
    return __fdividef(1.0f, 1.0f + __expf(-v));
}
static __device__ __forceinline__ float tanh_(float v) {
    float e = __expf(-2.0f * v);
    return __fdividef(2.0f, 1.0f + e) - 1.0f;
}

__global__ __launch_bounds__(NTHR, 1)
void lstm_kernel(const float* __restrict__ x,
                 const float* __restrict__ W_ih, const float* __restrict__ W_hh,
                 const float* __restrict__ b_ih, const float* __restrict__ b_hh,
                 const float* __restrict__ W_out, const float* __restrict__ b_out,
                 float* __restrict__ out)
{
    extern __shared__ char smem[];
    const uint32_t sb = smem_u32(smem);
    float* Gs = (float*)(smem + SM_GS);
    float* Hs = (float*)(smem + SM_HS);

    const int tid  = threadIdx.x;
    const int lane = tid & 31;
    const int warp = tid >> 5;
    const int b0   = blockIdx.x * MB;

    // ---- zero W / A staging (K padding + h0 = 0) ----
    for (int i = tid; i < (SM_GS - SM_WHI) / 4; i += NTHR)
        ((uint32_t*)smem)[i] = 0u;
    __syncthreads();

    // ---- stage W hi/lo: [gate][k] bf16 ----
    for (int idx = tid; idx < GG * KK; idx += NTHR) {
        int g = idx / KK, k = idx - g * KK;
        float v = (k < II) ? W_ih[g * II + k] : W_hh[g * HH + (k - II)];
        uint16_t hi, lo; split_bf16(v, hi, lo);
        *(uint16_t*)(smem + SM_WHI + (g * KST + k) * 2) = hi;
        *(uint16_t*)(smem + SM_WLO + (g * KST + k) * 2) = lo;
    }
    __syncthreads();

    if (warp < 8) {
        // ================= GEMM role (warps 0-7) =================
        const int gwarp = warp;            // 32-gate slice
        const int l7 = lane & 7, lg = lane >> 3;
        const int wrow = l7 + ((lg & 1) << 3);
        const int wkh  = lg >> 1;
        const uint32_t woffH = sb + SM_WHI + (((gwarp * 32 + wrow) * KST) + wkh * 8) * 2;
        const uint32_t woffL = sb + SM_WLO + (((gwarp * 32 + wrow) * KST) + wkh * 8) * 2;
        const int arow0 = l7 + ((lg >> 1) << 3);
        const int akh   = lg & 1;
        uint32_t aoffH[2], aoffL[2];
#pragma unroll
        for (int g = 0; g < 2; ++g) {
            aoffH[g] = sb + SM_AHI + (((g * 16 + arow0) * KST) + akh * 8) * 2;
            aoffL[g] = sb + SM_ALO + (((g * 16 + arow0) * KST) + akh * 8) * 2;
        }

        // W fragments resident in registers for the whole kernel
        uint32_t whiR[6][2][4], wloR[6][2][4];
#pragma unroll
        for (int kc = 0; kc < 6; ++kc)
#pragma unroll
            for (int mt = 0; mt < 2; ++mt) {
                LDSM4(whiR[kc][mt], woffH + mt * 16 * KST * 2 + kc * 32);
                LDSM4(wloR[kc][mt], woffL + mt * 16 * KST * 2 + kc * 32);
            }

        const int grow = lane >> 2;
        const int bcol = (lane & 3) * 2;
        float biasA[2], biasB[2];
#pragma unroll
        for (int mt = 0; mt < 2; ++mt) {
            int g1 = gwarp * 32 + mt * 16 + grow;
            biasA[mt] = b_ih[g1]     + b_hh[g1];
            biasB[mt] = b_ih[g1 + 8] + b_hh[g1 + 8];
        }

        for (int t = 0; t < TI; ++t) {
#pragma unroll
            for (int g = 0; g < 2; ++g) {
                BSYNC(1 + g);              // h(t-1,g) + x(t,g) ready
                float acc[2][2][4];
#pragma unroll
                for (int mt = 0; mt < 2; ++mt)
#pragma unroll
                    for (int j = 0; j < 2; ++j) {
                        acc[mt][j][0] = biasA[mt]; acc[mt][j][1] = biasA[mt];
                        acc[mt][j][2] = biasB[mt]; acc[mt][j][3] = biasB[mt];
                    }
#pragma unroll
                for (int kc = 0; kc < 6; ++kc) {
                    uint32_t bhi[4], blo[4];
                    LDSM4(bhi, aoffH[g] + kc * 32);
                    LDSM4(blo, aoffL[g] + kc * 32);
#pragma unroll
                    for (int mt = 0; mt < 2; ++mt)
#pragma unroll
                        for (int j = 0; j < 2; ++j) {
                            float* d = acc[mt][j];
                            MMA16816(d, whiR[kc][mt], bhi[2*j], bhi[2*j+1]);
                            MMA16816(d, whiR[kc][mt], blo[2*j], blo[2*j+1]);
                            MMA16816(d, wloR[kc][mt], bhi[2*j], bhi[2*j+1]);
                        }
                }
#pragma unroll
                for (int mt = 0; mt < 2; ++mt)
#pragma unroll
                    for (int j = 0; j < 2; ++j) {
                        const int g1 = gwarp * 32 + mt * 16 + grow;
                        const int bb = g * 16 + j * 8 + bcol;
                        Gs[g1 * GST + bb]           = acc[mt][j][0];
                        Gs[g1 * GST + bb + 1]       = acc[mt][j][1];
                        Gs[(g1 + 8) * GST + bb]     = acc[mt][j][2];
                        Gs[(g1 + 8) * GST + bb + 1] = acc[mt][j][3];
                    }
                BARR(3 + g);               // gates(t,g) ready
            }
        }
    } else {
        // ================= ACT role (warps 8-15) =================
        const int gtid = tid - 256;
        const int u  = gtid & 63;
        const int rb = (gtid >> 6) * 4;    // 4 rows per thread within group
        float cst[2][4];
#pragma unroll
        for (int g = 0; g < 2; ++g)
#pragma unroll
            for (int r = 0; r < 4; ++r) cst[g][r] = 0.0f;

        // prologue: stage x(0) for both groups (rows 0..31)
        if (gtid < 32 * 7) {
            int row = gtid / 7, seg = gtid % 7;
            const float4 xv = *reinterpret_cast<const float4*>(
                x + ((size_t)(b0 + row) * TI + 0) * II + seg * 4);
            uint16_t h0,l0,h1,l1,h2,l2,h3,l3;
            split_bf16(xv.x, h0, l0); split_bf16(xv.y, h1, l1);
            split_bf16(xv.z, h2, l2); split_bf16(xv.w, h3, l3);
            u64 ph = (u64)h0 | ((u64)h1 << 16) | ((u64)h2 << 32) | ((u64)h3 << 48);
            u64 pl = (u64)l0 | ((u64)l1 << 16) | ((u64)l2 << 32) | ((u64)l3 << 48);
            *(u64*)(smem + SM_AHI + (row * KST + seg * 4) * 2) = ph;
            *(u64*)(smem + SM_ALO + (row * KST + seg * 4) * 2) = pl;
        }
        BARR(1);                           // h(-1,A)=0 + x(0,A) ready
        BARR(2);                           // h(-1,B)=0 + x(0,B) ready

        for (int t = 0; t < TI; ++t) {
#pragma unroll
            for (int g = 0; g < 2; ++g) {
                BSYNC(3 + g);              // gates(t,g) ready
                // prefetch x(t+1, g) early (hide LDG latency under MUFU work)
                const bool st = (gtid < 16 * 7) && (t + 1 < TI);
                const int srow = g * 16 + gtid / 7, seg = gtid % 7;
                float4 xv;
                if (st)
                    xv = *reinterpret_cast<const float4*>(
                        x + ((size_t)(b0 + srow) * TI + (t + 1)) * II + seg * 4);
#pragma unroll
                for (int r = 0; r < 4; ++r) {
                    const int row = g * 16 + rb + r;
                    float ig = sigm_(Gs[u * GST + row]);
                    float fg = sigm_(Gs[(u + 64) * GST + row]);
                    float gg = tanh_(Gs[(u + 128) * GST + row]);
                    float og = sigm_(Gs[(u + 192) * GST + row]);
                    float cv = fmaf(fg, cst[g][r], ig * gg);
                    cst[g][r] = cv;
                    float hv = og * tanh_(cv);
                    uint16_t hh, hl; split_bf16(hv, hh, hl);
                    *(uint16_t*)(smem + SM_AHI + (row * KST + II + u) * 2) = hh;
                    *(uint16_t*)(smem + SM_ALO + (row * KST + II + u) * 2) = hl;
                    if (t == TI - 1) Hs[row * HH + u] = hv;
                }
                if (st) {
                    uint16_t h0,l0,h1,l1,h2,l2,h3,l3;
                    split_bf16(xv.x, h0, l0); split_bf16(xv.y, h1, l1);
                    split_bf16(xv.z, h2, l2); split_bf16(xv.w, h3, l3);
                    u64 ph = (u64)h0 | ((u64)h1 << 16) | ((u64)h2 << 32) | ((u64)h3 << 48);
                    u64 pl = (u64)l0 | ((u64)l1 << 16) | ((u64)l2 << 32) | ((u64)l3 << 48);
                    *(u64*)(smem + SM_AHI + (srow * KST + seg * 4) * 2) = ph;
                    *(u64*)(smem + SM_ALO + (srow * KST + seg * 4) * 2) = pl;
                }
                BARR(1 + g);               // h(t,g) + x(t+1,g) ready
            }
        }
    }

    // ---- final linear: out = h_T @ W_out^T + b_out ----
    __syncthreads();
    for (int idx = tid; idx < OUTD * HH; idx += NTHR) Gs[idx] = W_out[idx];
    if (tid < OUTD) Gs[OUTD * HH + tid] = b_out[tid];
    __syncthreads();

    for (int cell = tid; cell < MB * OUTD; cell += NTHR) {
        int row = cell / OUTD;
        int o   = cell - row * OUTD;
        float s = Gs[OUTD * HH + o];
#pragma unroll
        for (int j = 0; j < HH; ++j)
            s = fmaf(Hs[row * HH + j], Gs[o * HH + j], s);
        out[(size_t)(b0 + row) * OUTD + o] = s;
    }
}

extern "C" void kernel_launch(void* const* d_in, const int* in_sizes, int n_in,
                              void* d_out, int out_size)
{
    const float* x     = (const float*)d_in[0];
    const float* W_ih  = (const float*)d_in[1];
    const float* W_hh  = (const float*)d_in[2];
    const float* b_ih  = (const float*)d_in[3];
    const float* b_hh  = (const float*)d_in[4];
    const float* W_out = (const float*)d_in[5];
    const float* b_out = (const float*)d_in[6];
    float* outp = (float*)d_out;

    cudaFuncSetAttribute(lstm_kernel,
                         cudaFuncAttributeMaxDynamicSharedMemorySize, SMEM_BYTES);
    lstm_kernel<<<BB / MB, NTHR, SMEM_BYTES>>>(x, W_ih, W_hh, b_ih, b_hh,
                                               W_out, b_out, outp);
}